// round 3
// baseline (speedup 1.0000x reference)
#include <cuda_runtime.h>
#include <stdint.h>

#define WARPS_PER_BLOCK 4
#define NTHREADS (WARPS_PER_BLOCK * 32)
#define XST 33   // xs2 row stride in packed elements

typedef unsigned long long ull;

__device__ __forceinline__ ull pack2(float lo, float hi) {
    ull r; asm("mov.b64 %0, {%1, %2};" : "=l"(r) : "f"(lo), "f"(hi)); return r;
}
__device__ __forceinline__ void unpack2(ull v, float& lo, float& hi) {
    asm("mov.b64 {%0, %1}, %2;" : "=f"(lo), "=f"(hi) : "l"(v));
}
__device__ __forceinline__ ull fma2(ull a, ull b, ull c) {
    ull d; asm("fma.rn.f32x2 %0, %1, %2, %3;" : "=l"(d) : "l"(a), "l"(b), "l"(c)); return d;
}
__device__ __forceinline__ ull add2(ull a, ull b) {
    ull d; asm("add.rn.f32x2 %0, %1, %2;" : "=l"(d) : "l"(a), "l"(b)); return d;
}

// ---------------- precomputed weight-sign masks (written by prep kernel) ----------------
__device__ uint32_t g_br_pos[60];           // 18 (w3) + 36 (w4) + 6 (w6)
__device__ uint32_t g_c5_pos[16 * 120];     // [ch][o]

__global__ void prep_kernel(const float* __restrict__ w3,
                            const float* __restrict__ w4,
                            const float* __restrict__ w6,
                            const float* __restrict__ c5w) {
    int tid = blockIdx.x * blockDim.x + threadIdx.x;
    if (tid < 60) {
        const float* wp;
        if (tid < 18)      wp = w3 + tid * 25;
        else if (tid < 54) wp = w4 + (tid - 18) * 25;
        else               wp = w6 + (tid - 54) * 25;
        uint32_t m = 0;
        for (int i = 0; i < 25; i++) if (wp[i] > 0.0f) m |= (1u << i);
        g_br_pos[tid] = m;
    }
    for (int idx = tid; idx < 16 * 120; idx += blockDim.x * gridDim.x) {
        int ch = idx / 120, o = idx % 120;
        const float* wp = c5w + o * 400 + ch * 25;
        uint32_t m = 0;
        for (int i = 0; i < 25; i++) if (wp[i] > 0.0f) m |= (1u << i);
        g_c5_pos[idx] = m;
    }
}

// ---------------- fused forward kernel: one warp = TWO samples (f32x2 packed) ------------
struct WarpSmem {
    ull      xs2[32 * XST];        // packed (sampleA, sampleB) 32x32 tile
    ull      sf2[120];             // c5 outputs packed as +-1.0f pairs
    ull      yv2[84];              // f6 outputs packed
    uint8_t  posm8[2 * 6 * 28 * 4];// [s][ch][row][chunk] 7-bit chunk sign masks (u32-aligned rows)
    uint32_t b14[2 * 84];          // [s][ch*14+prow] pooled 14-bit rows
    uint32_t pix[2 * 100];         // [s][10x10] 16 branch bits per pixel
    uint32_t cb[2 * 16];           // [s][ch] stage-2 pooled 25-bit words
};
struct BlockSmem {
    WarpSmem w[WARPS_PER_BLOCK];
    ull      c1w2[150];            // c1 weights duplicated into both f32x2 halves
    ull      c1b2[6];              // c1 bias packed
    uint32_t c5pos[16 * 120];
    uint32_t brpos[60];
    float    brb[16];
    float    c5b[120];
};

__global__ __launch_bounds__(NTHREADS)
void lenet_kernel(const float* __restrict__ x,
                  const float* __restrict__ c1w_g, const float* __restrict__ c1b_g,
                  const float* __restrict__ b3,   const float* __restrict__ b4,
                  const float* __restrict__ b6,   const float* __restrict__ c5b_g,
                  const float* __restrict__ f6w,  const float* __restrict__ f6b,
                  const float* __restrict__ rbfw, const float* __restrict__ rbfb,
                  float* __restrict__ out, int nsamples) {
    extern __shared__ unsigned char smem_raw[];
    BlockSmem& S = *reinterpret_cast<BlockSmem*>(smem_raw);

    const int tid = threadIdx.x;
    for (int i = tid; i < 60; i += NTHREADS)       S.brpos[i] = g_br_pos[i];
    for (int i = tid; i < 16 * 120; i += NTHREADS) S.c5pos[i] = g_c5_pos[i];
    for (int i = tid; i < 150; i += NTHREADS)      { float w = c1w_g[i]; S.c1w2[i] = pack2(w, w); }
    for (int i = tid; i < 120; i += NTHREADS)      S.c5b[i] = c5b_g[i];
    if (tid < 6)        { float b = c1b_g[tid]; S.c1b2[tid] = pack2(b, b); }
    if (tid < 6)        S.brb[tid] = b3[tid];
    else if (tid < 15)  S.brb[tid] = b4[tid - 6];
    else if (tid == 15) S.brb[15]  = b6[0];
    __syncthreads();

    const int warp = tid >> 5, lane = tid & 31;
    const int sA = (blockIdx.x * WARPS_PER_BLOCK + warp) * 2;
    const int sB = sA + 1;
    if (sA >= nsamples) return;
    const bool validB = (sB < nsamples);
    WarpSmem& W = S.w[warp];

    // ---- load two x tiles, interleave into packed smem ----
    {
        const float4* xgA = reinterpret_cast<const float4*>(x + (size_t)sA * 1024);
        const float4* xgB = reinterpret_cast<const float4*>(x + (size_t)(validB ? sB : sA) * 1024);
        for (int i = lane; i < 256; i += 32) {
            float4 a = xgA[i], b = xgB[i];
            int e = i * 4;
            ull* p = W.xs2 + (e >> 5) * XST + (e & 31);
            p[0] = pack2(a.x, b.x); p[1] = pack2(a.y, b.y);
            p[2] = pack2(a.z, b.z); p[3] = pack2(a.w, b.w);
        }
    }
    __syncwarp();

    // ---- c1: packed fp32 conv; task = (row, 7-col chunk), ALL 6 channels per task ----
    // x window loaded ONCE per dy row and reused across 6 channels (6x fewer xv LDS).
    for (int t = lane; t < 112; t += 32) {
        const int row = t >> 2, chunk = t & 3;
        ull acc[6][7];
        #pragma unroll
        for (int ch = 0; ch < 6; ch++) {
            const ull b2 = S.c1b2[ch];
            #pragma unroll
            for (int j = 0; j < 7; j++) acc[ch][j] = b2;
        }
        const ull* xbase = W.xs2 + chunk * 7;
        #pragma unroll
        for (int dy = 0; dy < 5; dy++) {
            const ull* xr = xbase + (row + dy) * XST;
            ull xv[11];
            #pragma unroll
            for (int j = 0; j < 11; j++) xv[j] = xr[j];
            #pragma unroll
            for (int ch = 0; ch < 6; ch++) {
                #pragma unroll
                for (int k = 0; k < 5; k++) {
                    const ull w2 = S.c1w2[ch * 25 + dy * 5 + k];   // broadcast LDS
                    #pragma unroll
                    for (int col = 0; col < 7; col++)
                        acc[ch][col] = fma2(xv[col + k], w2, acc[ch][col]);
                }
            }
        }
        #pragma unroll
        for (int ch = 0; ch < 6; ch++) {
            uint32_t mA = 0, mB = 0;
            #pragma unroll
            for (int col = 0; col < 7; col++) {
                float a, b; unpack2(acc[ch][col], a, b);
                if (a > 0.0f) mA |= (1u << col);
                if (b > 0.0f) mB |= (1u << col);
            }
            const int base = ch * 112 + row * 4 + chunk;
            W.posm8[base]       = (uint8_t)mA;
            W.posm8[672 + base] = (uint8_t)mB;
        }
    }
    __syncwarp();

    // ---- stage-1 relu+avgpool+sign == OR over 2x2 bits, even-bit compress ----
    for (int v = lane; v < 168; v += 32) {
        const int s = (v >= 84) ? 1 : 0;
        const int u = s ? (v - 84) : v;
        const int ch = u / 14, pr = u % 14;
        const uint32_t* pm = reinterpret_cast<const uint32_t*>(W.posm8 + s * 672 + ch * 112);
        uint32_t v32 = pm[2 * pr] | pm[2 * pr + 1];   // OR the two rows; 4 chunk-bytes of 7 bits
        uint32_t m = (v32 & 0x7Fu)
                   | (((v32 >> 8)  & 0x7Fu) << 7)
                   | (((v32 >> 16) & 0x7Fu) << 14)
                   | (((v32 >> 24) & 0x7Fu) << 21);
        uint32_t c = (m | (m >> 1)) & 0x55555555u;
        c = (c | (c >> 1)) & 0x33333333u;
        c = (c | (c >> 2)) & 0x0F0F0F0Fu;
        c = (c | (c >> 4)) & 0x00FF00FFu;
        c = (c | (c >> 8)) & 0x0000FFFFu;
        W.b14[s * 84 + u] = c;
    }
    __syncwarp();

    // ---- 16 binary branch convs (bitpacked popcount), 200 pixel tasks ----
    {
        const int I3[18] = {0,1,2, 1,2,3, 2,3,4, 3,4,5, 0,4,5, 0,1,5};
        const int I4[36] = {0,1,2,3, 1,2,3,4, 2,3,4,5, 0,3,4,5, 0,1,4,5,
                            0,1,2,5, 0,1,3,4, 1,2,4,5, 0,2,3,5};
        for (int t = lane; t < 200; t += 32) {
            const int s = (t >= 100) ? 1 : 0;
            const int px = s ? (t - 100) : t;
            const int r = px / 10, c = px % 10;
            const uint32_t* bp = W.b14 + s * 84;
            uint32_t win[6]; int pc[6];
            #pragma unroll
            for (int ch = 0; ch < 6; ch++) {
                uint32_t wv = 0;
                #pragma unroll
                for (int dy = 0; dy < 5; dy++)
                    wv |= ((bp[ch * 14 + r + dy] >> c) & 31u) << (5 * dy);
                win[ch] = wv; pc[ch] = __popc(wv);
            }
            uint32_t bits = 0;
            #pragma unroll
            for (int k = 0; k < 6; k++) {
                const int a = I3[3*k], b = I3[3*k+1], d = I3[3*k+2];
                int sum = 2 * (__popc(win[a] & S.brpos[3*k])
                             + __popc(win[b] & S.brpos[3*k+1])
                             + __popc(win[d] & S.brpos[3*k+2]))
                          - (pc[a] + pc[b] + pc[d]);
                if ((float)sum + S.brb[k] > 0.0f) bits |= (1u << k);
            }
            #pragma unroll
            for (int k = 0; k < 9; k++) {
                const int a = I4[4*k], b = I4[4*k+1], d = I4[4*k+2], e = I4[4*k+3];
                int sum = 2 * (__popc(win[a] & S.brpos[18 + 4*k])
                             + __popc(win[b] & S.brpos[18 + 4*k+1])
                             + __popc(win[d] & S.brpos[18 + 4*k+2])
                             + __popc(win[e] & S.brpos[18 + 4*k+3]))
                          - (pc[a] + pc[b] + pc[d] + pc[e]);
                if ((float)sum + S.brb[6 + k] > 0.0f) bits |= (1u << (6 + k));
            }
            {
                int sum = 0;
                #pragma unroll
                for (int ch = 0; ch < 6; ch++)
                    sum += 2 * __popc(win[ch] & S.brpos[54 + ch]) - pc[ch];
                if ((float)sum + S.brb[15] > 0.0f) bits |= (1u << 15);
            }
            W.pix[s * 100 + px] = bits;
        }
    }
    __syncwarp();

    // ---- stage-2 relu+pool+sign -> 400 bits per sample, 32 lanes = 2s x 16ch ----
    {
        const int s = lane >> 4, ch = lane & 15;
        const uint32_t* pp = W.pix + s * 100;
        uint32_t r = 0;
        #pragma unroll
        for (int u = 0; u < 25; u++) {
            const int pr = u / 5, pc2 = u % 5;
            uint32_t v = pp[(2*pr) * 10 + 2*pc2]     | pp[(2*pr) * 10 + 2*pc2 + 1]
                       | pp[(2*pr + 1) * 10 + 2*pc2] | pp[(2*pr + 1) * 10 + 2*pc2 + 1];
            r |= ((v >> ch) & 1u) << u;
        }
        W.cb[s * 16 + ch] = r;
    }
    __syncwarp();

    // ---- c5: 120 binary dot products, both samples per task -> packed +-1 ----
    {
        int tpA = 0, tpB = 0;
        #pragma unroll
        for (int ch = 0; ch < 16; ch++) { tpA += __popc(W.cb[ch]); tpB += __popc(W.cb[16 + ch]); }
        for (int o = lane; o < 120; o += 32) {
            int aA = 0, aB = 0;
            #pragma unroll
            for (int ch = 0; ch < 16; ch++) {
                const uint32_t p = S.c5pos[ch * 120 + o];
                aA += __popc(W.cb[ch] & p);
                aB += __popc(W.cb[16 + ch] & p);
            }
            const float b = S.c5b[o];
            float vA = (float)(2 * aA - tpA) + b;
            float vB = (float)(2 * aB - tpB) + b;
            W.sf2[o] = pack2(vA > 0.0f ? 1.0f : -1.0f, vB > 0.0f ? 1.0f : -1.0f);
        }
    }
    __syncwarp();

    // ---- f6: y = tanh(1.7519 * (W s + b)), packed over both samples ----
    for (int i = lane; i < 84; i += 32) {
        const float4* wrow = reinterpret_cast<const float4*>(f6w + i * 120);
        ull a0 = 0, a1 = 0;
        #pragma unroll 6
        for (int j4 = 0; j4 < 30; j4++) {
            float4 wv = __ldg(wrow + j4);
            a0 = fma2(W.sf2[4*j4],     pack2(wv.x, wv.x), a0);
            a1 = fma2(W.sf2[4*j4 + 1], pack2(wv.y, wv.y), a1);
            a0 = fma2(W.sf2[4*j4 + 2], pack2(wv.z, wv.z), a0);
            a1 = fma2(W.sf2[4*j4 + 3], pack2(wv.w, wv.w), a1);
        }
        float gA, gB; unpack2(add2(a0, a1), gA, gB);
        const float fb = __ldg(f6b + i);
        W.yv2[i] = pack2(tanhf(1.7519f * (gA + fb)), tanhf(1.7519f * (gB + fb)));
    }
    __syncwarp();

    // ---- rbf head: relu(W y + b), packed ----
    if (lane < 10) {
        const float rb = __ldg(rbfb + lane);
        ull a0 = pack2(rb, rb), a1 = 0;
        const float* wr = rbfw + lane * 84;
        #pragma unroll 4
        for (int j = 0; j < 84; j += 2) {
            float w0 = __ldg(wr + j), w1 = __ldg(wr + j + 1);
            a0 = fma2(W.yv2[j],     pack2(w0, w0), a0);
            a1 = fma2(W.yv2[j + 1], pack2(w1, w1), a1);
        }
        float oA, oB; unpack2(add2(a0, a1), oA, oB);
        out[(size_t)sA * 10 + lane] = fmaxf(oA, 0.0f);
        if (validB) out[(size_t)sB * 10 + lane] = fmaxf(oB, 0.0f);
    }
}

extern "C" void kernel_launch(void* const* d_in, const int* in_sizes, int n_in,
                              void* d_out, int out_size) {
    const float* x    = (const float*)d_in[0];
    const float* c1w  = (const float*)d_in[1];
    const float* c1b  = (const float*)d_in[2];
    const float* w3   = (const float*)d_in[3];
    const float* b3   = (const float*)d_in[4];
    const float* w4   = (const float*)d_in[5];
    const float* b4   = (const float*)d_in[6];
    const float* w6   = (const float*)d_in[7];
    const float* b6   = (const float*)d_in[8];
    const float* c5w  = (const float*)d_in[9];
    const float* c5b  = (const float*)d_in[10];
    const float* f6w  = (const float*)d_in[11];
    const float* f6b  = (const float*)d_in[12];
    const float* rbfw = (const float*)d_in[13];
    const float* rbfb = (const float*)d_in[14];
    float* out = (float*)d_out;

    const int nsamples = in_sizes[0] / 1024;
    const int smem_bytes = (int)sizeof(BlockSmem);

    prep_kernel<<<8, 256>>>(w3, w4, w6, c5w);

    cudaFuncSetAttribute(lenet_kernel, cudaFuncAttributeMaxDynamicSharedMemorySize, smem_bytes);
    const int samples_per_block = WARPS_PER_BLOCK * 2;
    const int blocks = (nsamples + samples_per_block - 1) / samples_per_block;
    lenet_kernel<<<blocks, NTHREADS, smem_bytes>>>(
        x, c1w, c1b, b3, b4, b6, c5b, f6w, f6b, rbfw, rbfb, out, nsamples);
}

// round 4
// speedup vs baseline: 1.2903x; 1.2903x over previous
#include <cuda_runtime.h>
#include <stdint.h>

#define WARPS_PER_BLOCK 5
#define NTHREADS (WARPS_PER_BLOCK * 32)
#define XST 33   // xs2 row stride in packed elements

typedef unsigned long long ull;

__device__ __forceinline__ ull pack2(float lo, float hi) {
    ull r; asm("mov.b64 %0, {%1, %2};" : "=l"(r) : "f"(lo), "f"(hi)); return r;
}
__device__ __forceinline__ void unpack2(ull v, float& lo, float& hi) {
    asm("mov.b64 {%0, %1}, %2;" : "=f"(lo), "=f"(hi) : "l"(v));
}
__device__ __forceinline__ ull fma2(ull a, ull b, ull c) {
    ull d; asm("fma.rn.f32x2 %0, %1, %2, %3;" : "=l"(d) : "l"(a), "l"(b), "l"(c)); return d;
}
__device__ __forceinline__ ull add2(ull a, ull b) {
    ull d; asm("add.rn.f32x2 %0, %1, %2;" : "=l"(d) : "l"(a), "l"(b)); return d;
}

// ---------------- precomputed weight-sign masks (written by prep kernel) ----------------
__device__ uint32_t g_br_pos[60];           // 18 (w3) + 36 (w4) + 6 (w6)
__device__ uint32_t g_c5_pos[16 * 120];     // [ch][o]

__global__ void prep_kernel(const float* __restrict__ w3,
                            const float* __restrict__ w4,
                            const float* __restrict__ w6,
                            const float* __restrict__ c5w) {
    int tid = blockIdx.x * blockDim.x + threadIdx.x;
    if (tid < 60) {
        const float* wp;
        if (tid < 18)      wp = w3 + tid * 25;
        else if (tid < 54) wp = w4 + (tid - 18) * 25;
        else               wp = w6 + (tid - 54) * 25;
        uint32_t m = 0;
        for (int i = 0; i < 25; i++) if (wp[i] > 0.0f) m |= (1u << i);
        g_br_pos[tid] = m;
    }
    for (int idx = tid; idx < 16 * 120; idx += blockDim.x * gridDim.x) {
        int ch = idx / 120, o = idx % 120;
        const float* wp = c5w + o * 400 + ch * 25;
        uint32_t m = 0;
        for (int i = 0; i < 25; i++) if (wp[i] > 0.0f) m |= (1u << i);
        g_c5_pos[idx] = m;
    }
}

// ---------------- fused forward kernel: one warp = TWO samples (f32x2 packed) ------------
struct WarpSmem {
    ull      xs2[32 * XST];        // packed (sampleA, sampleB) 32x32 tile
    ull      sf2[120];             // c5 outputs packed as +-1.0f pairs
    ull      yv2[84];              // f6 outputs packed
    uint8_t  posm8[2 * 6 * 28 * 4];// [s][ch][row][chunk] 7-bit chunk sign masks (u32-aligned rows)
    uint32_t b14[2 * 84];          // [s][ch*14+prow] pooled 14-bit rows
    uint32_t pix[2 * 100];         // [s][10x10] 16 branch bits per pixel
    uint32_t cb[2 * 16];           // [s][ch] stage-2 pooled 25-bit words
};
struct BlockSmem {
    WarpSmem w[WARPS_PER_BLOCK];
    ull      c1w2[150];            // c1 weights duplicated into both f32x2 halves
    ull      c1b2[6];              // c1 bias packed
    uint32_t c5pos[16 * 120];
    uint32_t brpos[60];
    float    brb[16];
    float    c5b[120];
};

__global__ __launch_bounds__(NTHREADS)
void lenet_kernel(const float* __restrict__ x,
                  const float* __restrict__ c1w_g, const float* __restrict__ c1b_g,
                  const float* __restrict__ b3,   const float* __restrict__ b4,
                  const float* __restrict__ b6,   const float* __restrict__ c5b_g,
                  const float* __restrict__ f6w,  const float* __restrict__ f6b,
                  const float* __restrict__ rbfw, const float* __restrict__ rbfb,
                  float* __restrict__ out, int nsamples) {
    extern __shared__ unsigned char smem_raw[];
    BlockSmem& S = *reinterpret_cast<BlockSmem*>(smem_raw);

    const int tid = threadIdx.x;
    for (int i = tid; i < 60; i += NTHREADS)       S.brpos[i] = g_br_pos[i];
    for (int i = tid; i < 16 * 120; i += NTHREADS) S.c5pos[i] = g_c5_pos[i];
    for (int i = tid; i < 150; i += NTHREADS)      { float w = c1w_g[i]; S.c1w2[i] = pack2(w, w); }
    for (int i = tid; i < 120; i += NTHREADS)      S.c5b[i] = c5b_g[i];
    if (tid < 6)        { float b = c1b_g[tid]; S.c1b2[tid] = pack2(b, b); }
    if (tid < 6)        S.brb[tid] = b3[tid];
    else if (tid < 15)  S.brb[tid] = b4[tid - 6];
    else if (tid == 15) S.brb[15]  = b6[0];
    __syncthreads();

    const int warp = tid >> 5, lane = tid & 31;
    const int sA = (blockIdx.x * WARPS_PER_BLOCK + warp) * 2;
    const int sB = sA + 1;
    if (sA >= nsamples) return;
    const bool validB = (sB < nsamples);
    WarpSmem& W = S.w[warp];

    // ---- load two x tiles, interleave into packed smem ----
    {
        const float4* xgA = reinterpret_cast<const float4*>(x + (size_t)sA * 1024);
        const float4* xgB = reinterpret_cast<const float4*>(x + (size_t)(validB ? sB : sA) * 1024);
        for (int i = lane; i < 256; i += 32) {
            float4 a = xgA[i], b = xgB[i];
            int e = i * 4;
            ull* p = W.xs2 + (e >> 5) * XST + (e & 31);
            p[0] = pack2(a.x, b.x); p[1] = pack2(a.y, b.y);
            p[2] = pack2(a.z, b.z); p[3] = pack2(a.w, b.w);
        }
    }
    __syncwarp();

    // ---- c1: packed conv; task = (3-ch group, row, 7-col chunk); 224 tasks ----
    // x window loaded once per dy row, reused across 3 channels; acc[3][7]=42 regs (no spill).
    for (int t = lane; t < 224; t += 32) {
        const int g = (t >= 112) ? 1 : 0;
        const int rc = g ? (t - 112) : t;
        const int row = rc >> 2, chunk = rc & 3;
        const int ch0 = g * 3;
        ull acc[3][7];
        #pragma unroll
        for (int c = 0; c < 3; c++) {
            const ull b2 = S.c1b2[ch0 + c];
            #pragma unroll
            for (int j = 0; j < 7; j++) acc[c][j] = b2;
        }
        const ull* xbase = W.xs2 + chunk * 7;
        #pragma unroll
        for (int dy = 0; dy < 5; dy++) {
            const ull* xr = xbase + (row + dy) * XST;
            ull xv[11];
            #pragma unroll
            for (int j = 0; j < 11; j++) xv[j] = xr[j];
            #pragma unroll
            for (int c = 0; c < 3; c++) {
                #pragma unroll
                for (int k = 0; k < 5; k++) {
                    const ull w2 = S.c1w2[(ch0 + c) * 25 + dy * 5 + k];
                    #pragma unroll
                    for (int col = 0; col < 7; col++)
                        acc[c][col] = fma2(xv[col + k], w2, acc[c][col]);
                }
            }
        }
        #pragma unroll
        for (int c = 0; c < 3; c++) {
            uint32_t mA = 0, mB = 0;
            #pragma unroll
            for (int col = 0; col < 7; col++) {
                float a, b; unpack2(acc[c][col], a, b);
                if (a > 0.0f) mA |= (1u << col);
                if (b > 0.0f) mB |= (1u << col);
            }
            const int base = (ch0 + c) * 112 + row * 4 + chunk;
            W.posm8[base]       = (uint8_t)mA;
            W.posm8[672 + base] = (uint8_t)mB;
        }
    }
    __syncwarp();

    // ---- stage-1 relu+avgpool+sign == OR over 2x2 bits, even-bit compress ----
    for (int v = lane; v < 168; v += 32) {
        const int s = (v >= 84) ? 1 : 0;
        const int u = s ? (v - 84) : v;
        const int ch = u / 14, pr = u % 14;
        const uint32_t* pm = reinterpret_cast<const uint32_t*>(W.posm8 + s * 672 + ch * 112);
        uint32_t v32 = pm[2 * pr] | pm[2 * pr + 1];
        uint32_t m = (v32 & 0x7Fu)
                   | (((v32 >> 8)  & 0x7Fu) << 7)
                   | (((v32 >> 16) & 0x7Fu) << 14)
                   | (((v32 >> 24) & 0x7Fu) << 21);
        uint32_t c = (m | (m >> 1)) & 0x55555555u;
        c = (c | (c >> 1)) & 0x33333333u;
        c = (c | (c >> 2)) & 0x0F0F0F0Fu;
        c = (c | (c >> 4)) & 0x00FF00FFu;
        c = (c | (c >> 8)) & 0x0000FFFFu;
        W.b14[s * 84 + u] = c;
    }
    __syncwarp();

    // ---- 16 binary branch convs (bitpacked popcount), 200 pixel tasks ----
    {
        const int I3[18] = {0,1,2, 1,2,3, 2,3,4, 3,4,5, 0,4,5, 0,1,5};
        const int I4[36] = {0,1,2,3, 1,2,3,4, 2,3,4,5, 0,3,4,5, 0,1,4,5,
                            0,1,2,5, 0,1,3,4, 1,2,4,5, 0,2,3,5};
        for (int t = lane; t < 200; t += 32) {
            const int s = (t >= 100) ? 1 : 0;
            const int px = s ? (t - 100) : t;
            const int r = px / 10, c = px % 10;
            const uint32_t* bp = W.b14 + s * 84;
            uint32_t win[6]; int pc[6];
            #pragma unroll
            for (int ch = 0; ch < 6; ch++) {
                uint32_t wv = 0;
                #pragma unroll
                for (int dy = 0; dy < 5; dy++)
                    wv |= ((bp[ch * 14 + r + dy] >> c) & 31u) << (5 * dy);
                win[ch] = wv; pc[ch] = __popc(wv);
            }
            uint32_t bits = 0;
            #pragma unroll
            for (int k = 0; k < 6; k++) {
                const int a = I3[3*k], b = I3[3*k+1], d = I3[3*k+2];
                int sum = 2 * (__popc(win[a] & S.brpos[3*k])
                             + __popc(win[b] & S.brpos[3*k+1])
                             + __popc(win[d] & S.brpos[3*k+2]))
                          - (pc[a] + pc[b] + pc[d]);
                if ((float)sum + S.brb[k] > 0.0f) bits |= (1u << k);
            }
            #pragma unroll
            for (int k = 0; k < 9; k++) {
                const int a = I4[4*k], b = I4[4*k+1], d = I4[4*k+2], e = I4[4*k+3];
                int sum = 2 * (__popc(win[a] & S.brpos[18 + 4*k])
                             + __popc(win[b] & S.brpos[18 + 4*k+1])
                             + __popc(win[d] & S.brpos[18 + 4*k+2])
                             + __popc(win[e] & S.brpos[18 + 4*k+3]))
                          - (pc[a] + pc[b] + pc[d] + pc[e]);
                if ((float)sum + S.brb[6 + k] > 0.0f) bits |= (1u << (6 + k));
            }
            {
                int sum = 0;
                #pragma unroll
                for (int ch = 0; ch < 6; ch++)
                    sum += 2 * __popc(win[ch] & S.brpos[54 + ch]) - pc[ch];
                if ((float)sum + S.brb[15] > 0.0f) bits |= (1u << 15);
            }
            W.pix[s * 100 + px] = bits;
        }
    }
    __syncwarp();

    // ---- stage-2 relu+pool+sign -> 400 bits per sample, 32 lanes = 2s x 16ch ----
    {
        const int s = lane >> 4, ch = lane & 15;
        const uint32_t* pp = W.pix + s * 100;
        uint32_t r = 0;
        #pragma unroll
        for (int u = 0; u < 25; u++) {
            const int pr = u / 5, pc2 = u % 5;
            uint32_t v = pp[(2*pr) * 10 + 2*pc2]     | pp[(2*pr) * 10 + 2*pc2 + 1]
                       | pp[(2*pr + 1) * 10 + 2*pc2] | pp[(2*pr + 1) * 10 + 2*pc2 + 1];
            r |= ((v >> ch) & 1u) << u;
        }
        W.cb[s * 16 + ch] = r;
    }
    __syncwarp();

    // ---- c5: 120 binary dot products, both samples per task -> packed +-1 ----
    {
        int tpA = 0, tpB = 0;
        #pragma unroll
        for (int ch = 0; ch < 16; ch++) { tpA += __popc(W.cb[ch]); tpB += __popc(W.cb[16 + ch]); }
        for (int o = lane; o < 120; o += 32) {
            int aA = 0, aB = 0;
            #pragma unroll
            for (int ch = 0; ch < 16; ch++) {
                const uint32_t p = S.c5pos[ch * 120 + o];
                aA += __popc(W.cb[ch] & p);
                aB += __popc(W.cb[16 + ch] & p);
            }
            const float b = S.c5b[o];
            float vA = (float)(2 * aA - tpA) + b;
            float vB = (float)(2 * aB - tpB) + b;
            W.sf2[o] = pack2(vA > 0.0f ? 1.0f : -1.0f, vB > 0.0f ? 1.0f : -1.0f);
        }
    }
    __syncwarp();

    // ---- f6: y = tanh(1.7519 * (W s + b)), packed over both samples ----
    for (int i = lane; i < 84; i += 32) {
        const float4* wrow = reinterpret_cast<const float4*>(f6w + i * 120);
        ull a0 = 0, a1 = 0;
        #pragma unroll 6
        for (int j4 = 0; j4 < 30; j4++) {
            float4 wv = __ldg(wrow + j4);
            a0 = fma2(W.sf2[4*j4],     pack2(wv.x, wv.x), a0);
            a1 = fma2(W.sf2[4*j4 + 1], pack2(wv.y, wv.y), a1);
            a0 = fma2(W.sf2[4*j4 + 2], pack2(wv.z, wv.z), a0);
            a1 = fma2(W.sf2[4*j4 + 3], pack2(wv.w, wv.w), a1);
        }
        float gA, gB; unpack2(add2(a0, a1), gA, gB);
        const float fb = __ldg(f6b + i);
        W.yv2[i] = pack2(tanhf(1.7519f * (gA + fb)), tanhf(1.7519f * (gB + fb)));
    }
    __syncwarp();

    // ---- rbf head: relu(W y + b), packed ----
    if (lane < 10) {
        const float rb = __ldg(rbfb + lane);
        ull a0 = pack2(rb, rb), a1 = 0;
        const float* wr = rbfw + lane * 84;
        #pragma unroll 4
        for (int j = 0; j < 84; j += 2) {
            float w0 = __ldg(wr + j), w1 = __ldg(wr + j + 1);
            a0 = fma2(W.yv2[j],     pack2(w0, w0), a0);
            a1 = fma2(W.yv2[j + 1], pack2(w1, w1), a1);
        }
        float oA, oB; unpack2(add2(a0, a1), oA, oB);
        out[(size_t)sA * 10 + lane] = fmaxf(oA, 0.0f);
        if (validB) out[(size_t)sB * 10 + lane] = fmaxf(oB, 0.0f);
    }
}

extern "C" void kernel_launch(void* const* d_in, const int* in_sizes, int n_in,
                              void* d_out, int out_size) {
    const float* x    = (const float*)d_in[0];
    const float* c1w  = (const float*)d_in[1];
    const float* c1b  = (const float*)d_in[2];
    const float* w3   = (const float*)d_in[3];
    const float* b3   = (const float*)d_in[4];
    const float* w4   = (const float*)d_in[5];
    const float* b4   = (const float*)d_in[6];
    const float* w6   = (const float*)d_in[7];
    const float* b6   = (const float*)d_in[8];
    const float* c5w  = (const float*)d_in[9];
    const float* c5b  = (const float*)d_in[10];
    const float* f6w  = (const float*)d_in[11];
    const float* f6b  = (const float*)d_in[12];
    const float* rbfw = (const float*)d_in[13];
    const float* rbfb = (const float*)d_in[14];
    float* out = (float*)d_out;

    const int nsamples = in_sizes[0] / 1024;
    const int smem_bytes = (int)sizeof(BlockSmem);

    prep_kernel<<<8, 256>>>(w3, w4, w6, c5w);

    cudaFuncSetAttribute(lenet_kernel, cudaFuncAttributeMaxDynamicSharedMemorySize, smem_bytes);
    const int samples_per_block = WARPS_PER_BLOCK * 2;
    const int blocks = (nsamples + samples_per_block - 1) / samples_per_block;
    lenet_kernel<<<blocks, NTHREADS, smem_bytes>>>(
        x, c1w, c1b, b3, b4, b6, c5b, f6w, f6b, rbfw, rbfb, out, nsamples);
}

// round 5
// speedup vs baseline: 1.4763x; 1.1442x over previous
#include <cuda_runtime.h>
#include <stdint.h>

#define WARPS_PER_BLOCK 4
#define NTHREADS (WARPS_PER_BLOCK * 32)
#define MINBLOCKS 3          // reg cap 65536/(128*3) = 170: fits c1 (~110 regs) spill-free
#define XST 33               // xs2 row stride in packed elements

typedef unsigned long long ull;

__device__ __forceinline__ ull pack2(float lo, float hi) {
    ull r; asm("mov.b64 %0, {%1, %2};" : "=l"(r) : "f"(lo), "f"(hi)); return r;
}
__device__ __forceinline__ void unpack2(ull v, float& lo, float& hi) {
    asm("mov.b64 {%0, %1}, %2;" : "=f"(lo), "=f"(hi) : "l"(v));
}
__device__ __forceinline__ ull fma2(ull a, ull b, ull c) {
    ull d; asm("fma.rn.f32x2 %0, %1, %2, %3;" : "=l"(d) : "l"(a), "l"(b), "l"(c)); return d;
}
__device__ __forceinline__ ull add2(ull a, ull b) {
    ull d; asm("add.rn.f32x2 %0, %1, %2;" : "=l"(d) : "l"(a), "l"(b)); return d;
}

// ---------------- precomputed weight-sign masks (written by prep kernel) ----------------
__device__ uint32_t g_br_pos[60];           // 18 (w3) + 36 (w4) + 6 (w6)
__device__ uint32_t g_c5_pos[16 * 120];     // [ch][o]

__global__ void prep_kernel(const float* __restrict__ w3,
                            const float* __restrict__ w4,
                            const float* __restrict__ w6,
                            const float* __restrict__ c5w) {
    int tid = blockIdx.x * blockDim.x + threadIdx.x;
    if (tid < 60) {
        const float* wp;
        if (tid < 18)      wp = w3 + tid * 25;
        else if (tid < 54) wp = w4 + (tid - 18) * 25;
        else               wp = w6 + (tid - 54) * 25;
        uint32_t m = 0;
        for (int i = 0; i < 25; i++) if (wp[i] > 0.0f) m |= (1u << i);
        g_br_pos[tid] = m;
    }
    for (int idx = tid; idx < 16 * 120; idx += blockDim.x * gridDim.x) {
        int ch = idx / 120, o = idx % 120;
        const float* wp = c5w + o * 400 + ch * 25;
        uint32_t m = 0;
        for (int i = 0; i < 25; i++) if (wp[i] > 0.0f) m |= (1u << i);
        g_c5_pos[idx] = m;
    }
}

// ---------------- fused forward kernel: one warp = TWO samples (f32x2 packed) ------------
struct WarpSmem {
    ull      xs2[32 * XST];        // packed (sampleA, sampleB) 32x32 tile
    ull      sf2[120];             // c5 outputs packed as +-1.0f pairs
    ull      yv2[84];              // f6 outputs packed
    uint8_t  posm8[2 * 6 * 28 * 4];// [s][ch][row][chunk] 7-bit chunk sign masks (u32-aligned rows)
    uint32_t b14[2 * 84];          // [s][ch*14+prow] pooled 14-bit rows
    uint32_t pix[2 * 100];         // [s][10x10] 16 branch bits per pixel
    uint32_t cb[2 * 16];           // [s][ch] stage-2 pooled 25-bit words
};
struct BlockSmem {
    WarpSmem w[WARPS_PER_BLOCK];
    ull      c1w2[150];            // c1 weights duplicated into both f32x2 halves
    ull      c1b2[6];              // c1 bias packed
    uint32_t c5pos[16 * 120];
    uint32_t brpos[60];
    float    brb[16];
    float    c5b[120];
};

__global__ __launch_bounds__(NTHREADS, MINBLOCKS)
void lenet_kernel(const float* __restrict__ x,
                  const float* __restrict__ c1w_g, const float* __restrict__ c1b_g,
                  const float* __restrict__ b3,   const float* __restrict__ b4,
                  const float* __restrict__ b6,   const float* __restrict__ c5b_g,
                  const float* __restrict__ f6w,  const float* __restrict__ f6b,
                  const float* __restrict__ rbfw, const float* __restrict__ rbfb,
                  float* __restrict__ out, int nsamples) {
    extern __shared__ unsigned char smem_raw[];
    BlockSmem& S = *reinterpret_cast<BlockSmem*>(smem_raw);

    const int tid = threadIdx.x;
    for (int i = tid; i < 60; i += NTHREADS)       S.brpos[i] = g_br_pos[i];
    for (int i = tid; i < 16 * 120; i += NTHREADS) S.c5pos[i] = g_c5_pos[i];
    for (int i = tid; i < 150; i += NTHREADS)      { float w = c1w_g[i]; S.c1w2[i] = pack2(w, w); }
    for (int i = tid; i < 120; i += NTHREADS)      S.c5b[i] = c5b_g[i];
    if (tid < 6)        { float b = c1b_g[tid]; S.c1b2[tid] = pack2(b, b); }
    if (tid < 6)        S.brb[tid] = b3[tid];
    else if (tid < 15)  S.brb[tid] = b4[tid - 6];
    else if (tid == 15) S.brb[15]  = b6[0];
    __syncthreads();

    const int warp = tid >> 5, lane = tid & 31;
    const int sA = (blockIdx.x * WARPS_PER_BLOCK + warp) * 2;
    const int sB = sA + 1;
    if (sA >= nsamples) return;
    const bool validB = (sB < nsamples);
    WarpSmem& W = S.w[warp];

    // ---- load two x tiles, interleave into packed smem ----
    {
        const float4* xgA = reinterpret_cast<const float4*>(x + (size_t)sA * 1024);
        const float4* xgB = reinterpret_cast<const float4*>(x + (size_t)(validB ? sB : sA) * 1024);
        for (int i = lane; i < 256; i += 32) {
            float4 a = xgA[i], b = xgB[i];
            int e = i * 4;
            ull* p = W.xs2 + (e >> 5) * XST + (e & 31);
            p[0] = pack2(a.x, b.x); p[1] = pack2(a.y, b.y);
            p[2] = pack2(a.z, b.z); p[3] = pack2(a.w, b.w);
        }
    }
    __syncwarp();

    // ---- c1: packed conv; task = (3-ch group, row, 7-col chunk); 224 tasks ----
    // x window loaded once per dy row, reused across 3 channels.
    for (int t = lane; t < 224; t += 32) {
        const int g = (t >= 112) ? 1 : 0;
        const int rc = g ? (t - 112) : t;
        const int row = rc >> 2, chunk = rc & 3;
        const int ch0 = g * 3;
        ull acc[3][7];
        #pragma unroll
        for (int c = 0; c < 3; c++) {
            const ull b2 = S.c1b2[ch0 + c];
            #pragma unroll
            for (int j = 0; j < 7; j++) acc[c][j] = b2;
        }
        const ull* xbase = W.xs2 + chunk * 7;
        #pragma unroll
        for (int dy = 0; dy < 5; dy++) {
            const ull* xr = xbase + (row + dy) * XST;
            ull xv[11];
            #pragma unroll
            for (int j = 0; j < 11; j++) xv[j] = xr[j];
            #pragma unroll
            for (int c = 0; c < 3; c++) {
                #pragma unroll
                for (int k = 0; k < 5; k++) {
                    const ull w2 = S.c1w2[(ch0 + c) * 25 + dy * 5 + k];
                    #pragma unroll
                    for (int col = 0; col < 7; col++)
                        acc[c][col] = fma2(xv[col + k], w2, acc[c][col]);
                }
            }
        }
        #pragma unroll
        for (int c = 0; c < 3; c++) {
            uint32_t mA = 0, mB = 0;
            #pragma unroll
            for (int col = 0; col < 7; col++) {
                float a, b; unpack2(acc[c][col], a, b);
                if (a > 0.0f) mA |= (1u << col);
                if (b > 0.0f) mB |= (1u << col);
            }
            const int base = (ch0 + c) * 112 + row * 4 + chunk;
            W.posm8[base]       = (uint8_t)mA;
            W.posm8[672 + base] = (uint8_t)mB;
        }
    }
    __syncwarp();

    // ---- stage-1 relu+avgpool+sign == OR over 2x2 bits, even-bit compress ----
    for (int v = lane; v < 168; v += 32) {
        const int s = (v >= 84) ? 1 : 0;
        const int u = s ? (v - 84) : v;
        const int ch = u / 14, pr = u % 14;
        const uint32_t* pm = reinterpret_cast<const uint32_t*>(W.posm8 + s * 672 + ch * 112);
        uint32_t v32 = pm[2 * pr] | pm[2 * pr + 1];
        uint32_t m = (v32 & 0x7Fu)
                   | (((v32 >> 8)  & 0x7Fu) << 7)
                   | (((v32 >> 16) & 0x7Fu) << 14)
                   | (((v32 >> 24) & 0x7Fu) << 21);
        uint32_t c = (m | (m >> 1)) & 0x55555555u;
        c = (c | (c >> 1)) & 0x33333333u;
        c = (c | (c >> 2)) & 0x0F0F0F0Fu;
        c = (c | (c >> 4)) & 0x00FF00FFu;
        c = (c | (c >> 8)) & 0x0000FFFFu;
        W.b14[s * 84 + u] = c;
    }
    __syncwarp();

    // ---- 16 binary branch convs (bitpacked popcount), 200 pixel tasks ----
    {
        const int I3[18] = {0,1,2, 1,2,3, 2,3,4, 3,4,5, 0,4,5, 0,1,5};
        const int I4[36] = {0,1,2,3, 1,2,3,4, 2,3,4,5, 0,3,4,5, 0,1,4,5,
                            0,1,2,5, 0,1,3,4, 1,2,4,5, 0,2,3,5};
        for (int t = lane; t < 200; t += 32) {
            const int s = (t >= 100) ? 1 : 0;
            const int px = s ? (t - 100) : t;
            const int r = px / 10, c = px % 10;
            const uint32_t* bp = W.b14 + s * 84;
            uint32_t win[6]; int pc[6];
            #pragma unroll
            for (int ch = 0; ch < 6; ch++) {
                uint32_t wv = 0;
                #pragma unroll
                for (int dy = 0; dy < 5; dy++)
                    wv |= ((bp[ch * 14 + r + dy] >> c) & 31u) << (5 * dy);
                win[ch] = wv; pc[ch] = __popc(wv);
            }
            uint32_t bits = 0;
            #pragma unroll
            for (int k = 0; k < 6; k++) {
                const int a = I3[3*k], b = I3[3*k+1], d = I3[3*k+2];
                int sum = 2 * (__popc(win[a] & S.brpos[3*k])
                             + __popc(win[b] & S.brpos[3*k+1])
                             + __popc(win[d] & S.brpos[3*k+2]))
                          - (pc[a] + pc[b] + pc[d]);
                if ((float)sum + S.brb[k] > 0.0f) bits |= (1u << k);
            }
            #pragma unroll
            for (int k = 0; k < 9; k++) {
                const int a = I4[4*k], b = I4[4*k+1], d = I4[4*k+2], e = I4[4*k+3];
                int sum = 2 * (__popc(win[a] & S.brpos[18 + 4*k])
                             + __popc(win[b] & S.brpos[18 + 4*k+1])
                             + __popc(win[d] & S.brpos[18 + 4*k+2])
                             + __popc(win[e] & S.brpos[18 + 4*k+3]))
                          - (pc[a] + pc[b] + pc[d] + pc[e]);
                if ((float)sum + S.brb[6 + k] > 0.0f) bits |= (1u << (6 + k));
            }
            {
                int sum = 0;
                #pragma unroll
                for (int ch = 0; ch < 6; ch++)
                    sum += 2 * __popc(win[ch] & S.brpos[54 + ch]) - pc[ch];
                if ((float)sum + S.brb[15] > 0.0f) bits |= (1u << 15);
            }
            W.pix[s * 100 + px] = bits;
        }
    }
    __syncwarp();

    // ---- stage-2 relu+pool+sign -> 400 bits per sample, 32 lanes = 2s x 16ch ----
    {
        const int s = lane >> 4, ch = lane & 15;
        const uint32_t* pp = W.pix + s * 100;
        uint32_t r = 0;
        #pragma unroll
        for (int u = 0; u < 25; u++) {
            const int pr = u / 5, pc2 = u % 5;
            uint32_t v = pp[(2*pr) * 10 + 2*pc2]     | pp[(2*pr) * 10 + 2*pc2 + 1]
                       | pp[(2*pr + 1) * 10 + 2*pc2] | pp[(2*pr + 1) * 10 + 2*pc2 + 1];
            r |= ((v >> ch) & 1u) << u;
        }
        W.cb[s * 16 + ch] = r;
    }
    __syncwarp();

    // ---- c5: 120 binary dot products, both samples per task -> packed +-1 ----
    {
        int tpA = 0, tpB = 0;
        #pragma unroll
        for (int ch = 0; ch < 16; ch++) { tpA += __popc(W.cb[ch]); tpB += __popc(W.cb[16 + ch]); }
        for (int o = lane; o < 120; o += 32) {
            int aA = 0, aB = 0;
            #pragma unroll
            for (int ch = 0; ch < 16; ch++) {
                const uint32_t p = S.c5pos[ch * 120 + o];
                aA += __popc(W.cb[ch] & p);
                aB += __popc(W.cb[16 + ch] & p);
            }
            const float b = S.c5b[o];
            float vA = (float)(2 * aA - tpA) + b;
            float vB = (float)(2 * aB - tpB) + b;
            W.sf2[o] = pack2(vA > 0.0f ? 1.0f : -1.0f, vB > 0.0f ? 1.0f : -1.0f);
        }
    }
    __syncwarp();

    // ---- f6: y = tanh(1.7519 * (W s + b)), packed over both samples ----
    for (int i = lane; i < 84; i += 32) {
        const float4* wrow = reinterpret_cast<const float4*>(f6w + i * 120);
        ull a0 = 0, a1 = 0;
        #pragma unroll 6
        for (int j4 = 0; j4 < 30; j4++) {
            float4 wv = __ldg(wrow + j4);
            a0 = fma2(W.sf2[4*j4],     pack2(wv.x, wv.x), a0);
            a1 = fma2(W.sf2[4*j4 + 1], pack2(wv.y, wv.y), a1);
            a0 = fma2(W.sf2[4*j4 + 2], pack2(wv.z, wv.z), a0);
            a1 = fma2(W.sf2[4*j4 + 3], pack2(wv.w, wv.w), a1);
        }
        float gA, gB; unpack2(add2(a0, a1), gA, gB);
        const float fb = __ldg(f6b + i);
        W.yv2[i] = pack2(tanhf(1.7519f * (gA + fb)), tanhf(1.7519f * (gB + fb)));
    }
    __syncwarp();

    // ---- rbf head: relu(W y + b), packed ----
    if (lane < 10) {
        const float rb = __ldg(rbfb + lane);
        ull a0 = pack2(rb, rb), a1 = 0;
        const float* wr = rbfw + lane * 84;
        #pragma unroll 4
        for (int j = 0; j < 84; j += 2) {
            float w0 = __ldg(wr + j), w1 = __ldg(wr + j + 1);
            a0 = fma2(W.yv2[j],     pack2(w0, w0), a0);
            a1 = fma2(W.yv2[j + 1], pack2(w1, w1), a1);
        }
        float oA, oB; unpack2(add2(a0, a1), oA, oB);
        out[(size_t)sA * 10 + lane] = fmaxf(oA, 0.0f);
        if (validB) out[(size_t)sB * 10 + lane] = fmaxf(oB, 0.0f);
    }
}

extern "C" void kernel_launch(void* const* d_in, const int* in_sizes, int n_in,
                              void* d_out, int out_size) {
    const float* x    = (const float*)d_in[0];
    const float* c1w  = (const float*)d_in[1];
    const float* c1b  = (const float*)d_in[2];
    const float* w3   = (const float*)d_in[3];
    const float* b3   = (const float*)d_in[4];
    const float* w4   = (const float*)d_in[5];
    const float* b4   = (const float*)d_in[6];
    const float* w6   = (const float*)d_in[7];
    const float* b6   = (const float*)d_in[8];
    const float* c5w  = (const float*)d_in[9];
    const float* c5b  = (const float*)d_in[10];
    const float* f6w  = (const float*)d_in[11];
    const float* f6b  = (const float*)d_in[12];
    const float* rbfw = (const float*)d_in[13];
    const float* rbfb = (const float*)d_in[14];
    float* out = (float*)d_out;

    const int nsamples = in_sizes[0] / 1024;
    const int smem_bytes = (int)sizeof(BlockSmem);

    prep_kernel<<<8, 256>>>(w3, w4, w6, c5w);

    cudaFuncSetAttribute(lenet_kernel, cudaFuncAttributeMaxDynamicSharedMemorySize, smem_bytes);
    const int samples_per_block = WARPS_PER_BLOCK * 2;
    const int blocks = (nsamples + samples_per_block - 1) / samples_per_block;
    lenet_kernel<<<blocks, NTHREADS, smem_bytes>>>(
        x, c1w, c1b, b3, b4, b6, c5b, f6w, f6b, rbfw, rbfb, out, nsamples);
}

// round 6
// speedup vs baseline: 1.5523x; 1.0515x over previous
#include <cuda_runtime.h>
#include <stdint.h>

#define WARPS_PER_BLOCK 4
#define NTHREADS (WARPS_PER_BLOCK * 32)
#define MINBLOCKS 4          // reg cap 65536/(128*4) = 128; 4 blocks/SM = 16 warps/SM
#define XST 33               // xs2 row stride in packed elements

typedef unsigned long long ull;

__device__ __forceinline__ ull pack2(float lo, float hi) {
    ull r; asm("mov.b64 %0, {%1, %2};" : "=l"(r) : "f"(lo), "f"(hi)); return r;
}
__device__ __forceinline__ void unpack2(ull v, float& lo, float& hi) {
    asm("mov.b64 {%0, %1}, %2;" : "=f"(lo), "=f"(hi) : "l"(v));
}
__device__ __forceinline__ ull fma2(ull a, ull b, ull c) {
    ull d; asm("fma.rn.f32x2 %0, %1, %2, %3;" : "=l"(d) : "l"(a), "l"(b), "l"(c)); return d;
}
__device__ __forceinline__ ull add2(ull a, ull b) {
    ull d; asm("add.rn.f32x2 %0, %1, %2;" : "=l"(d) : "l"(a), "l"(b)); return d;
}

// ---------------- precomputed weight-sign masks (written by prep kernel) ----------------
__device__ uint32_t g_br_pos[60];           // 18 (w3) + 36 (w4) + 6 (w6)
__device__ uint32_t g_c5_pos[16 * 120];     // [ch][o]

__global__ void prep_kernel(const float* __restrict__ w3,
                            const float* __restrict__ w4,
                            const float* __restrict__ w6,
                            const float* __restrict__ c5w) {
    int tid = blockIdx.x * blockDim.x + threadIdx.x;
    if (tid < 60) {
        const float* wp;
        if (tid < 18)      wp = w3 + tid * 25;
        else if (tid < 54) wp = w4 + (tid - 18) * 25;
        else               wp = w6 + (tid - 54) * 25;
        uint32_t m = 0;
        for (int i = 0; i < 25; i++) if (wp[i] > 0.0f) m |= (1u << i);
        g_br_pos[tid] = m;
    }
    for (int idx = tid; idx < 16 * 120; idx += blockDim.x * gridDim.x) {
        int ch = idx / 120, o = idx % 120;
        const float* wp = c5w + o * 400 + ch * 25;
        uint32_t m = 0;
        for (int i = 0; i < 25; i++) if (wp[i] > 0.0f) m |= (1u << i);
        g_c5_pos[idx] = m;
    }
}

// ---------------- fused forward kernel: one warp = TWO samples (f32x2 packed) ------------
// xs2 is only live during c1; all post-c1 buffers overlay it (posm8 must coexist).
struct LateSmem {
    ull      sf2[120];             // c5 outputs packed as +-1.0f pairs
    ull      yv2[84];              // f6 outputs packed
    uint32_t b14[2 * 84];          // [s][ch*14+prow] pooled 14-bit rows
    uint32_t pix[2 * 100];         // [s][10x10] 16 branch bits per pixel
    uint32_t cb[2 * 16];           // [s][ch] stage-2 pooled 25-bit words
};
struct WarpSmem {
    union {
        ull      xs2[32 * XST];    // packed (sampleA, sampleB) 32x32 tile (c1 phase only)
        LateSmem L;                // post-c1 buffers
    };
    uint8_t  posm8[2 * 6 * 28 * 4];// [s][ch][row][chunk] 7-bit chunk sign masks
};
struct BlockSmem {
    WarpSmem w[WARPS_PER_BLOCK];
    ull      c1w2[150];            // c1 weights duplicated into both f32x2 halves
    ull      c1b2[6];              // c1 bias packed
    uint32_t c5pos[16 * 120];
    uint32_t brpos[60];
    float    brb[16];
    float    c5b[120];
};

__global__ __launch_bounds__(NTHREADS, MINBLOCKS)
void lenet_kernel(const float* __restrict__ x,
                  const float* __restrict__ c1w_g, const float* __restrict__ c1b_g,
                  const float* __restrict__ b3,   const float* __restrict__ b4,
                  const float* __restrict__ b6,   const float* __restrict__ c5b_g,
                  const float* __restrict__ f6w,  const float* __restrict__ f6b,
                  const float* __restrict__ rbfw, const float* __restrict__ rbfb,
                  float* __restrict__ out, int nsamples) {
    extern __shared__ unsigned char smem_raw[];
    BlockSmem& S = *reinterpret_cast<BlockSmem*>(smem_raw);

    const int tid = threadIdx.x;
    for (int i = tid; i < 60; i += NTHREADS)       S.brpos[i] = g_br_pos[i];
    for (int i = tid; i < 16 * 120; i += NTHREADS) S.c5pos[i] = g_c5_pos[i];
    for (int i = tid; i < 150; i += NTHREADS)      { float w = c1w_g[i]; S.c1w2[i] = pack2(w, w); }
    for (int i = tid; i < 120; i += NTHREADS)      S.c5b[i] = c5b_g[i];
    if (tid < 6)        { float b = c1b_g[tid]; S.c1b2[tid] = pack2(b, b); }
    if (tid < 6)        S.brb[tid] = b3[tid];
    else if (tid < 15)  S.brb[tid] = b4[tid - 6];
    else if (tid == 15) S.brb[15]  = b6[0];
    __syncthreads();

    const int warp = tid >> 5, lane = tid & 31;
    const int sA = (blockIdx.x * WARPS_PER_BLOCK + warp) * 2;
    const int sB = sA + 1;
    if (sA >= nsamples) return;
    const bool validB = (sB < nsamples);
    WarpSmem& W = S.w[warp];

    // ---- load two x tiles, interleave into packed smem ----
    {
        const float4* xgA = reinterpret_cast<const float4*>(x + (size_t)sA * 1024);
        const float4* xgB = reinterpret_cast<const float4*>(x + (size_t)(validB ? sB : sA) * 1024);
        for (int i = lane; i < 256; i += 32) {
            float4 a = xgA[i], b = xgB[i];
            int e = i * 4;
            ull* p = W.xs2 + (e >> 5) * XST + (e & 31);
            p[0] = pack2(a.x, b.x); p[1] = pack2(a.y, b.y);
            p[2] = pack2(a.z, b.z); p[3] = pack2(a.w, b.w);
        }
    }
    __syncwarp();

    // ---- c1: packed conv; task = (3-ch group, row, 7-col chunk); 224 tasks ----
    for (int t = lane; t < 224; t += 32) {
        const int g = (t >= 112) ? 1 : 0;
        const int rc = g ? (t - 112) : t;
        const int row = rc >> 2, chunk = rc & 3;
        const int ch0 = g * 3;
        ull acc[3][7];
        #pragma unroll
        for (int c = 0; c < 3; c++) {
            const ull b2 = S.c1b2[ch0 + c];
            #pragma unroll
            for (int j = 0; j < 7; j++) acc[c][j] = b2;
        }
        const ull* xbase = W.xs2 + chunk * 7;
        #pragma unroll
        for (int dy = 0; dy < 5; dy++) {
            const ull* xr = xbase + (row + dy) * XST;
            ull xv[11];
            #pragma unroll
            for (int j = 0; j < 11; j++) xv[j] = xr[j];
            #pragma unroll
            for (int c = 0; c < 3; c++) {
                #pragma unroll
                for (int k = 0; k < 5; k++) {
                    const ull w2 = S.c1w2[(ch0 + c) * 25 + dy * 5 + k];
                    #pragma unroll
                    for (int col = 0; col < 7; col++)
                        acc[c][col] = fma2(xv[col + k], w2, acc[c][col]);
                }
            }
        }
        #pragma unroll
        for (int c = 0; c < 3; c++) {
            uint32_t mA = 0, mB = 0;
            #pragma unroll
            for (int col = 0; col < 7; col++) {
                float a, b; unpack2(acc[c][col], a, b);
                if (a > 0.0f) mA |= (1u << col);
                if (b > 0.0f) mB |= (1u << col);
            }
            const int base = (ch0 + c) * 112 + row * 4 + chunk;
            W.posm8[base]       = (uint8_t)mA;
            W.posm8[672 + base] = (uint8_t)mB;
        }
    }
    __syncwarp();   // xs2 dead from here; W.L overlays it

    // ---- stage-1 relu+avgpool+sign == OR over 2x2 bits, even-bit compress ----
    for (int v = lane; v < 168; v += 32) {
        const int s = (v >= 84) ? 1 : 0;
        const int u = s ? (v - 84) : v;
        const int ch = u / 14, pr = u % 14;
        const uint32_t* pm = reinterpret_cast<const uint32_t*>(W.posm8 + s * 672 + ch * 112);
        uint32_t v32 = pm[2 * pr] | pm[2 * pr + 1];
        uint32_t m = (v32 & 0x7Fu)
                   | (((v32 >> 8)  & 0x7Fu) << 7)
                   | (((v32 >> 16) & 0x7Fu) << 14)
                   | (((v32 >> 24) & 0x7Fu) << 21);
        uint32_t c = (m | (m >> 1)) & 0x55555555u;
        c = (c | (c >> 1)) & 0x33333333u;
        c = (c | (c >> 2)) & 0x0F0F0F0Fu;
        c = (c | (c >> 4)) & 0x00FF00FFu;
        c = (c | (c >> 8)) & 0x0000FFFFu;
        W.L.b14[s * 84 + u] = c;
    }
    __syncwarp();

    // ---- 16 binary branch convs (bitpacked popcount), 200 pixel tasks ----
    {
        const int I3[18] = {0,1,2, 1,2,3, 2,3,4, 3,4,5, 0,4,5, 0,1,5};
        const int I4[36] = {0,1,2,3, 1,2,3,4, 2,3,4,5, 0,3,4,5, 0,1,4,5,
                            0,1,2,5, 0,1,3,4, 1,2,4,5, 0,2,3,5};
        for (int t = lane; t < 200; t += 32) {
            const int s = (t >= 100) ? 1 : 0;
            const int px = s ? (t - 100) : t;
            const int r = px / 10, c = px % 10;
            const uint32_t* bp = W.L.b14 + s * 84;
            uint32_t win[6]; int pc[6];
            #pragma unroll
            for (int ch = 0; ch < 6; ch++) {
                uint32_t wv = 0;
                #pragma unroll
                for (int dy = 0; dy < 5; dy++)
                    wv |= ((bp[ch * 14 + r + dy] >> c) & 31u) << (5 * dy);
                win[ch] = wv; pc[ch] = __popc(wv);
            }
            uint32_t bits = 0;
            #pragma unroll
            for (int k = 0; k < 6; k++) {
                const int a = I3[3*k], b = I3[3*k+1], d = I3[3*k+2];
                int sum = 2 * (__popc(win[a] & S.brpos[3*k])
                             + __popc(win[b] & S.brpos[3*k+1])
                             + __popc(win[d] & S.brpos[3*k+2]))
                          - (pc[a] + pc[b] + pc[d]);
                if ((float)sum + S.brb[k] > 0.0f) bits |= (1u << k);
            }
            #pragma unroll
            for (int k = 0; k < 9; k++) {
                const int a = I4[4*k], b = I4[4*k+1], d = I4[4*k+2], e = I4[4*k+3];
                int sum = 2 * (__popc(win[a] & S.brpos[18 + 4*k])
                             + __popc(win[b] & S.brpos[18 + 4*k+1])
                             + __popc(win[d] & S.brpos[18 + 4*k+2])
                             + __popc(win[e] & S.brpos[18 + 4*k+3]))
                          - (pc[a] + pc[b] + pc[d] + pc[e]);
                if ((float)sum + S.brb[6 + k] > 0.0f) bits |= (1u << (6 + k));
            }
            {
                int sum = 0;
                #pragma unroll
                for (int ch = 0; ch < 6; ch++)
                    sum += 2 * __popc(win[ch] & S.brpos[54 + ch]) - pc[ch];
                if ((float)sum + S.brb[15] > 0.0f) bits |= (1u << 15);
            }
            W.L.pix[s * 100 + px] = bits;
        }
    }
    __syncwarp();

    // ---- stage-2 relu+pool+sign -> 400 bits per sample, 32 lanes = 2s x 16ch ----
    {
        const int s = lane >> 4, ch = lane & 15;
        const uint32_t* pp = W.L.pix + s * 100;
        uint32_t r = 0;
        #pragma unroll
        for (int u = 0; u < 25; u++) {
            const int pr = u / 5, pc2 = u % 5;
            uint32_t v = pp[(2*pr) * 10 + 2*pc2]     | pp[(2*pr) * 10 + 2*pc2 + 1]
                       | pp[(2*pr + 1) * 10 + 2*pc2] | pp[(2*pr + 1) * 10 + 2*pc2 + 1];
            r |= ((v >> ch) & 1u) << u;
        }
        W.L.cb[s * 16 + ch] = r;
    }
    __syncwarp();

    // ---- c5: 120 binary dot products, both samples per task -> packed +-1 ----
    {
        int tpA = 0, tpB = 0;
        #pragma unroll
        for (int ch = 0; ch < 16; ch++) { tpA += __popc(W.L.cb[ch]); tpB += __popc(W.L.cb[16 + ch]); }
        for (int o = lane; o < 120; o += 32) {
            int aA = 0, aB = 0;
            #pragma unroll
            for (int ch = 0; ch < 16; ch++) {
                const uint32_t p = S.c5pos[ch * 120 + o];
                aA += __popc(W.L.cb[ch] & p);
                aB += __popc(W.L.cb[16 + ch] & p);
            }
            const float b = S.c5b[o];
            float vA = (float)(2 * aA - tpA) + b;
            float vB = (float)(2 * aB - tpB) + b;
            W.L.sf2[o] = pack2(vA > 0.0f ? 1.0f : -1.0f, vB > 0.0f ? 1.0f : -1.0f);
        }
    }
    __syncwarp();

    // ---- f6: y = tanh(1.7519 * (W s + b)), packed over both samples ----
    for (int i = lane; i < 84; i += 32) {
        const float4* wrow = reinterpret_cast<const float4*>(f6w + i * 120);
        ull a0 = 0, a1 = 0;
        #pragma unroll 6
        for (int j4 = 0; j4 < 30; j4++) {
            float4 wv = __ldg(wrow + j4);
            a0 = fma2(W.L.sf2[4*j4],     pack2(wv.x, wv.x), a0);
            a1 = fma2(W.L.sf2[4*j4 + 1], pack2(wv.y, wv.y), a1);
            a0 = fma2(W.L.sf2[4*j4 + 2], pack2(wv.z, wv.z), a0);
            a1 = fma2(W.L.sf2[4*j4 + 3], pack2(wv.w, wv.w), a1);
        }
        float gA, gB; unpack2(add2(a0, a1), gA, gB);
        const float fb = __ldg(f6b + i);
        W.L.yv2[i] = pack2(tanhf(1.7519f * (gA + fb)), tanhf(1.7519f * (gB + fb)));
    }
    __syncwarp();

    // ---- rbf head: relu(W y + b), packed ----
    if (lane < 10) {
        const float rb = __ldg(rbfb + lane);
        ull a0 = pack2(rb, rb), a1 = 0;
        const float* wr = rbfw + lane * 84;
        #pragma unroll 4
        for (int j = 0; j < 84; j += 2) {
            float w0 = __ldg(wr + j), w1 = __ldg(wr + j + 1);
            a0 = fma2(W.L.yv2[j],     pack2(w0, w0), a0);
            a1 = fma2(W.L.yv2[j + 1], pack2(w1, w1), a1);
        }
        float oA, oB; unpack2(add2(a0, a1), oA, oB);
        out[(size_t)sA * 10 + lane] = fmaxf(oA, 0.0f);
        if (validB) out[(size_t)sB * 10 + lane] = fmaxf(oB, 0.0f);
    }
}

extern "C" void kernel_launch(void* const* d_in, const int* in_sizes, int n_in,
                              void* d_out, int out_size) {
    const float* x    = (const float*)d_in[0];
    const float* c1w  = (const float*)d_in[1];
    const float* c1b  = (const float*)d_in[2];
    const float* w3   = (const float*)d_in[3];
    const float* b3   = (const float*)d_in[4];
    const float* w4   = (const float*)d_in[5];
    const float* b4   = (const float*)d_in[6];
    const float* w6   = (const float*)d_in[7];
    const float* b6   = (const float*)d_in[8];
    const float* c5w  = (const float*)d_in[9];
    const float* c5b  = (const float*)d_in[10];
    const float* f6w  = (const float*)d_in[11];
    const float* f6b  = (const float*)d_in[12];
    const float* rbfw = (const float*)d_in[13];
    const float* rbfb = (const float*)d_in[14];
    float* out = (float*)d_out;

    const int nsamples = in_sizes[0] / 1024;
    const int smem_bytes = (int)sizeof(BlockSmem);

    prep_kernel<<<8, 256>>>(w3, w4, w6, c5w);

    cudaFuncSetAttribute(lenet_kernel, cudaFuncAttributeMaxDynamicSharedMemorySize, smem_bytes);
    const int samples_per_block = WARPS_PER_BLOCK * 2;
    const int blocks = (nsamples + samples_per_block - 1) / samples_per_block;
    lenet_kernel<<<blocks, NTHREADS, smem_bytes>>>(
        x, c1w, c1b, b3, b4, b6, c5b, f6w, f6b, rbfw, rbfb, out, nsamples);
}